// round 9
// baseline (speedup 1.0000x reference)
#include <cuda_runtime.h>
#include <cuda_fp16.h>
#include <math.h>

#define BATCH 4096
#define FEAT  40960
#define HID   1024
#define HID2  2048
#define NL1   64
#define NL2   32
#define GRP   32
#define NGRP  (BATCH / GRP)     // 128

// ---------------- static device scratch (no allocs allowed) ----------------
__device__ __half g_ftT[(size_t)FEAT * HID];    // 83.9 MB: ft_w^T [FEAT][HID] fp16
__device__ __half g_h1[(size_t)BATCH * HID2];   // 16.8 MB: clipped FT output fp16
__device__ int    g_done;                       // transpose-completion counter
__device__ int    g_grp[NGRP];                  // per-group h1-completion counters

// =========================================================================
// Reset kernel
// =========================================================================
__global__ void reset_kernel()
{
    if (threadIdx.x < NGRP) g_grp[threadIdx.x] = 0;
    if (threadIdx.x == 0)   g_done = 0;
}

// =========================================================================
// Mega-kernel, three CTA classes by blockIdx:
//   [0, NT)                 : transpose ft_w -> g_ftT (fp16), signal g_done.
//   [NT, NT+BATCH)          : scan -> wait g_done -> gather -> h1 -> bump g_grp.
//   [NT+BATCH, +NGRP)       : wait g_grp[g]==32 -> 32-row MLP -> out.
// =========================================================================
#define T1      256
#define NT      512
#define MAXIDX  256
#define NTILE_F (FEAT / 32)                 // 1280
#define NTILES  (NTILE_F * (HID / 64))      // 20480
#define MCHUNK  32
#define MNCH    (HID2 / MCHUNK)             // 64

__global__ __launch_bounds__(T1) void mega_kernel(
    const float* __restrict__ wf,    // [B, FEAT]
    const float* __restrict__ bfeat, // [B, FEAT]
    const float* __restrict__ stm,   // [B, 1]
    const float* __restrict__ ftw,   // [HID, FEAT]
    const float* __restrict__ ft_b,  // [HID]
    const float* __restrict__ l1_w,  // [64, 2048]
    const float* __restrict__ l1_b,  // [64]
    const float* __restrict__ l2_w,  // [32, 64]
    const float* __restrict__ l2_b,  // [32]
    const float* __restrict__ l3_w,  // [1, 32]
    const float* __restrict__ l3_b,  // [1]
    float* __restrict__ out, int out_size)
{
    __shared__ union {
        float tile[64][33];                                   // transpose (8.4 KB)
        struct { int idxW[MAXIDX]; int idxB[MAXIDX]; int cw; int cb; } s;
        struct {                                              // MLP (21.4 KB peak)
            union {
                struct {
                    __align__(16) float hst[MCHUNK][36];      // 4.6 KB
                    __align__(16) float wst[MCHUNK][66];      // 8.4 KB
                } l1;
                float h3[GRP][NL2 + 1];                       // 4.2 KB
            } u;
            float h2[GRP][NL1 + 1];                           // 8.3 KB
        } m;
    } sm;

    const int tid = threadIdx.x;

    // ===================== class 1: transpose =====================
    if (blockIdx.x < NT) {
        for (int t = blockIdx.x; t < NTILES; t += NT) {
            const int f0 = (t % NTILE_F) * 32;
            const int h0 = (t / NTILE_F) * 64;
#pragma unroll
            for (int u = 0; u < 8; u++) {
                int idx = tid + u * T1;
                int hl = idx >> 5, fl = idx & 31;
                sm.tile[hl][fl] = __ldcs(ftw + (size_t)(h0 + hl) * FEAT + f0 + fl);
            }
            __syncthreads();
#pragma unroll
            for (int u = 0; u < 4; u++) {
                int idx = tid + u * T1;
                int fl = idx >> 5, hp = idx & 31;
                __half2 v = __floats2half2_rn(sm.tile[2 * hp][fl], sm.tile[2 * hp + 1][fl]);
                *reinterpret_cast<__half2*>(g_ftT + (size_t)(f0 + fl) * HID + h0 + 2 * hp) = v;
            }
            __syncthreads();
        }
        __threadfence();
        __syncthreads();
        if (tid == 0) atomicAdd(&g_done, 1);
        return;
    }

    // ===================== class 3: group MLP =====================
    if (blockIdx.x >= NT + BATCH) {
        const int g = blockIdx.x - (NT + BATCH);
        if (tid == 0) {
            while (atomicAdd(&g_grp[g], 0) < GRP) __nanosleep(64);
        }
        __syncthreads();
        __threadfence();

        const int row0 = g * GRP;
        const int tx = tid & 31;      // out pair {2tx, 2tx+1}
        const int ty = tid >> 5;      // row quad {4ty..4ty+3}

        float acc[4][2];
#pragma unroll
        for (int i = 0; i < 4; i++) { acc[i][0] = 0.f; acc[i][1] = 0.f; }

        for (int c = 0; c < MNCH; c++) {
            const int kc = c * MCHUNK;
            __syncthreads();
            // hst: 32 rows x 32 k -> [k][r]; 512 half2, 2/thread
#pragma unroll
            for (int u = 0; u < 2; u++) {
                int idx = tid + u * T1; int r = idx >> 4, kp = idx & 15;
                float2 f = __half22float2(*reinterpret_cast<const __half2*>(
                    g_h1 + (size_t)(row0 + r) * HID2 + kc + 2 * kp));
                sm.m.u.l1.hst[2 * kp][r]     = f.x;
                sm.m.u.l1.hst[2 * kp + 1][r] = f.y;
            }
            // wst: 64 o x 32 k -> [k][o]; 2048 floats, 8/thread
#pragma unroll
            for (int u = 0; u < 8; u++) {
                int idx = tid + u * T1; int oo = idx >> 5, kk = idx & 31;
                sm.m.u.l1.wst[kk][oo] = __ldg(l1_w + (size_t)oo * HID2 + kc + kk);
            }
            __syncthreads();
#pragma unroll
            for (int k = 0; k < MCHUNK; k++) {
                const float4 h = *reinterpret_cast<const float4*>(&sm.m.u.l1.hst[k][4 * ty]);
                const float2 w = *reinterpret_cast<const float2*>(&sm.m.u.l1.wst[k][2 * tx]);
                acc[0][0] = fmaf(h.x, w.x, acc[0][0]); acc[0][1] = fmaf(h.x, w.y, acc[0][1]);
                acc[1][0] = fmaf(h.y, w.x, acc[1][0]); acc[1][1] = fmaf(h.y, w.y, acc[1][1]);
                acc[2][0] = fmaf(h.z, w.x, acc[2][0]); acc[2][1] = fmaf(h.z, w.y, acc[2][1]);
                acc[3][0] = fmaf(h.w, w.x, acc[3][0]); acc[3][1] = fmaf(h.w, w.y, acc[3][1]);
            }
        }
        __syncthreads();

        // h2 = clip(l1 + bias)
#pragma unroll
        for (int i = 0; i < 4; i++) {
#pragma unroll
            for (int j = 0; j < 2; j++) {
                float v = acc[i][j] + __ldg(l1_b + 2 * tx + j);
                sm.m.h2[4 * ty + i][2 * tx + j] = fminf(fmaxf(v, 0.f), 1.f);
            }
        }
        __syncthreads();

        // l2: 32 rows x 32 outs = 1024 -> 4/thread; weights straight from L2
        for (int p = tid; p < GRP * NL2; p += T1) {
            int r = p >> 5, oo = p & 31;
            float s = __ldg(l2_b + oo);
            const float* wrow = l2_w + oo * NL1;
#pragma unroll
            for (int k = 0; k < NL1; k++) s = fmaf(sm.m.h2[r][k], __ldg(wrow + k), s);
            sm.m.u.h3[r][oo] = fminf(fmaxf(s, 0.f), 1.f);
        }
        __syncthreads();

        // l3 + sigmoid
        if (tid < GRP) {
            float s = __ldg(l3_b);
#pragma unroll
            for (int k = 0; k < NL2; k++) s = fmaf(sm.m.u.h3[tid][k], __ldg(l3_w + k), s);
            float sig = 1.f / (1.f + expf(-s));
            int r = row0 + tid;
            if (out_size >= 2 * BATCH) {
                out[r]         = sig;
                out[BATCH + r] = s;
            } else {
                out[r] = sig;
            }
        }
        return;
    }

    // ===================== class 2: scan + gather =====================
    const int b = blockIdx.x - NT;

    if (tid == 0) { sm.s.cw = 0; sm.s.cb = 0; }
    __syncthreads();
    {
        const float4* pw = (const float4*)(wf    + (size_t)b * FEAT);
        const float4* pb = (const float4*)(bfeat + (size_t)b * FEAT);
        for (int base = 0; base < FEAT / 4; base += 4 * T1) {
            float4 v[4], w[4];
#pragma unroll
            for (int u = 0; u < 4; u++) {
                v[u] = __ldcs(pw + base + tid + u * T1);
                w[u] = __ldcs(pb + base + tid + u * T1);
            }
#pragma unroll
            for (int u = 0; u < 4; u++) {
                int i = base + tid + u * T1;
                if (v[u].x != 0.f) { int q = atomicAdd(&sm.s.cw, 1); if (q < MAXIDX) sm.s.idxW[q] = 4*i;   }
                if (v[u].y != 0.f) { int q = atomicAdd(&sm.s.cw, 1); if (q < MAXIDX) sm.s.idxW[q] = 4*i+1; }
                if (v[u].z != 0.f) { int q = atomicAdd(&sm.s.cw, 1); if (q < MAXIDX) sm.s.idxW[q] = 4*i+2; }
                if (v[u].w != 0.f) { int q = atomicAdd(&sm.s.cw, 1); if (q < MAXIDX) sm.s.idxW[q] = 4*i+3; }
                if (w[u].x != 0.f) { int q = atomicAdd(&sm.s.cb, 1); if (q < MAXIDX) sm.s.idxB[q] = 4*i;   }
                if (w[u].y != 0.f) { int q = atomicAdd(&sm.s.cb, 1); if (q < MAXIDX) sm.s.idxB[q] = 4*i+1; }
                if (w[u].z != 0.f) { int q = atomicAdd(&sm.s.cb, 1); if (q < MAXIDX) sm.s.idxB[q] = 4*i+2; }
                if (w[u].w != 0.f) { int q = atomicAdd(&sm.s.cb, 1); if (q < MAXIDX) sm.s.idxB[q] = 4*i+3; }
            }
        }
    }
    __syncthreads();

    // wait for transpose completion
    if (tid == 0) {
        while (atomicAdd(&g_done, 0) < NT) __nanosleep(128);
    }
    __syncthreads();
    __threadfence();

    // gather
    const float4 bias = *reinterpret_cast<const float4*>(ft_b + 4 * tid);
    float4 accW = bias, accB = bias;
    const int nW = min(sm.s.cw, MAXIDX);
#pragma unroll 4
    for (int j = 0; j < nW; j++) {
        const uint2 raw = *reinterpret_cast<const uint2*>(
            g_ftT + (size_t)sm.s.idxW[j] * HID + 4 * tid);
        const float2 lo = __half22float2(*reinterpret_cast<const __half2*>(&raw.x));
        const float2 hi = __half22float2(*reinterpret_cast<const __half2*>(&raw.y));
        accW.x += lo.x; accW.y += lo.y; accW.z += hi.x; accW.w += hi.y;
    }
    const int nB = min(sm.s.cb, MAXIDX);
#pragma unroll 4
    for (int j = 0; j < nB; j++) {
        const uint2 raw = *reinterpret_cast<const uint2*>(
            g_ftT + (size_t)sm.s.idxB[j] * HID + 4 * tid);
        const float2 lo = __half22float2(*reinterpret_cast<const __half2*>(&raw.x));
        const float2 hi = __half22float2(*reinterpret_cast<const __half2*>(&raw.y));
        accB.x += lo.x; accB.y += lo.y; accB.z += hi.x; accB.w += hi.y;
    }

    // stm select + clip + store h1 (fp16)
    const float s = __ldg(stm + b);
    float cw[4] = {fminf(fmaxf(accW.x,0.f),1.f), fminf(fmaxf(accW.y,0.f),1.f),
                   fminf(fmaxf(accW.z,0.f),1.f), fminf(fmaxf(accW.w,0.f),1.f)};
    float cb[4] = {fminf(fmaxf(accB.x,0.f),1.f), fminf(fmaxf(accB.y,0.f),1.f),
                   fminf(fmaxf(accB.z,0.f),1.f), fminf(fmaxf(accB.w,0.f),1.f)};
    __half* o = g_h1 + (size_t)b * HID2;
    uint2 pf, ps;
    *reinterpret_cast<__half2*>(&pf.x) = __floats2half2_rn(
        s*cw[0]+(1.f-s)*cb[0], s*cw[1]+(1.f-s)*cb[1]);
    *reinterpret_cast<__half2*>(&pf.y) = __floats2half2_rn(
        s*cw[2]+(1.f-s)*cb[2], s*cw[3]+(1.f-s)*cb[3]);
    *reinterpret_cast<__half2*>(&ps.x) = __floats2half2_rn(
        s*cb[0]+(1.f-s)*cw[0], s*cb[1]+(1.f-s)*cw[1]);
    *reinterpret_cast<__half2*>(&ps.y) = __floats2half2_rn(
        s*cb[2]+(1.f-s)*cw[2], s*cb[3]+(1.f-s)*cw[3]);
    *reinterpret_cast<uint2*>(o + 4 * tid)       = pf;
    *reinterpret_cast<uint2*>(o + HID + 4 * tid) = ps;

    // publish h1 and signal group completion
    __threadfence();
    __syncthreads();
    if (tid == 0) atomicAdd(&g_grp[b >> 5], 1);
}

// =========================================================================
extern "C" void kernel_launch(void* const* d_in, const int* in_sizes, int n_in,
                              void* d_out, int out_size)
{
    const float* wf    = (const float*)d_in[0];
    const float* bfeat = (const float*)d_in[1];
    const float* stm   = (const float*)d_in[2];
    const float* ft_w  = (const float*)d_in[3];
    const float* ft_b  = (const float*)d_in[4];
    const float* l1_w  = (const float*)d_in[5];
    const float* l1_b  = (const float*)d_in[6];
    const float* l2_w  = (const float*)d_in[7];
    const float* l2_b  = (const float*)d_in[8];
    const float* l3_w  = (const float*)d_in[9];
    const float* l3_b  = (const float*)d_in[10];
    float* out = (float*)d_out;

    reset_kernel<<<1, 128>>>();
    mega_kernel<<<NT + BATCH + NGRP, T1>>>(wf, bfeat, stm, ft_w, ft_b,
                                           l1_w, l1_b, l2_w, l2_b, l3_w, l3_b,
                                           out, out_size);
}

// round 10
// speedup vs baseline: 1.4953x; 1.4953x over previous
#include <cuda_runtime.h>
#include <cuda_fp16.h>
#include <math.h>

#define BATCH 4096
#define FEAT  40960
#define HID   1024
#define HID2  2048
#define NL1   64
#define NL2   32

// ---------------- static device scratch (no allocs allowed) ----------------
__device__ __half g_ftT[(size_t)FEAT * HID];    // 83.9 MB: ft_w^T [FEAT][HID] fp16
__device__ __half g_h1[(size_t)BATCH * HID2];   // 16.8 MB: clipped FT output fp16
__device__ int    g_done;                       // transpose-completion counter

// =========================================================================
// Reset kernel
// =========================================================================
__global__ void reset_kernel() { g_done = 0; }

// =========================================================================
// Mega-kernel (round-4 proven structure):
//   CTAs [0, NT)        : transpose ft_w -> g_ftT (fp16), signal.
//   CTAs [NT, NT+BATCH) : scan -> wait -> gather -> h1 (fp16).
// Scan uses a single OR-test per float4 (features are exactly 0.0/1.0).
// =========================================================================
#define T1      256
#define NT      512
#define MAXIDX  256
#define NTILE_F (FEAT / 32)                 // 1280
#define NTILES  (NTILE_F * (HID / 64))      // 20480

__global__ __launch_bounds__(T1) void mega_kernel(
    const float* __restrict__ wf,    // [B, FEAT]
    const float* __restrict__ bfeat, // [B, FEAT]
    const float* __restrict__ stm,   // [B, 1]
    const float* __restrict__ ftw,   // [HID, FEAT]
    const float* __restrict__ ft_b)  // [HID]
{
    __shared__ union {
        float tile[64][33];
        struct { int idxW[MAXIDX]; int idxB[MAXIDX]; int cw; int cb; } s;
    } sm;

    const int tid = threadIdx.x;

    if (blockIdx.x < NT) {
        // ---------------- transpose: 40 tiles of 64h x 32f per CTA ----------------
        for (int t = blockIdx.x; t < NTILES; t += NT) {
            const int f0 = (t % NTILE_F) * 32;
            const int h0 = (t / NTILE_F) * 64;
#pragma unroll
            for (int u = 0; u < 8; u++) {
                int idx = tid + u * T1;
                int hl = idx >> 5, fl = idx & 31;
                sm.tile[hl][fl] = __ldcs(ftw + (size_t)(h0 + hl) * FEAT + f0 + fl);
            }
            __syncthreads();
#pragma unroll
            for (int u = 0; u < 4; u++) {
                int idx = tid + u * T1;
                int fl = idx >> 5, hp = idx & 31;
                __half2 v = __floats2half2_rn(sm.tile[2 * hp][fl], sm.tile[2 * hp + 1][fl]);
                *reinterpret_cast<__half2*>(g_ftT + (size_t)(f0 + fl) * HID + h0 + 2 * hp) = v;
            }
            __syncthreads();
        }
        __threadfence();
        __syncthreads();
        if (tid == 0) atomicAdd(&g_done, 1);
        return;
    }

    // ---------------- scan ----------------
    const int b = blockIdx.x - NT;

    if (tid == 0) { sm.s.cw = 0; sm.s.cb = 0; }
    __syncthreads();
    {
        const uint4* pw = (const uint4*)(wf    + (size_t)b * FEAT);
        const uint4* pb = (const uint4*)(bfeat + (size_t)b * FEAT);
        for (int base = 0; base < FEAT / 4; base += 4 * T1) {
            uint4 v[4], w[4];
#pragma unroll
            for (int u = 0; u < 4; u++) {
                v[u] = __ldcs(pw + base + tid + u * T1);
                w[u] = __ldcs(pb + base + tid + u * T1);
            }
#pragma unroll
            for (int u = 0; u < 4; u++) {
                int i = base + tid + u * T1;
                // features are exactly 0.0f / 1.0f -> bit-pattern test is exact
                if (v[u].x | v[u].y | v[u].z | v[u].w) {
                    if (v[u].x) { int q = atomicAdd(&sm.s.cw, 1); if (q < MAXIDX) sm.s.idxW[q] = 4*i;   }
                    if (v[u].y) { int q = atomicAdd(&sm.s.cw, 1); if (q < MAXIDX) sm.s.idxW[q] = 4*i+1; }
                    if (v[u].z) { int q = atomicAdd(&sm.s.cw, 1); if (q < MAXIDX) sm.s.idxW[q] = 4*i+2; }
                    if (v[u].w) { int q = atomicAdd(&sm.s.cw, 1); if (q < MAXIDX) sm.s.idxW[q] = 4*i+3; }
                }
                if (w[u].x | w[u].y | w[u].z | w[u].w) {
                    if (w[u].x) { int q = atomicAdd(&sm.s.cb, 1); if (q < MAXIDX) sm.s.idxB[q] = 4*i;   }
                    if (w[u].y) { int q = atomicAdd(&sm.s.cb, 1); if (q < MAXIDX) sm.s.idxB[q] = 4*i+1; }
                    if (w[u].z) { int q = atomicAdd(&sm.s.cb, 1); if (q < MAXIDX) sm.s.idxB[q] = 4*i+2; }
                    if (w[u].w) { int q = atomicAdd(&sm.s.cb, 1); if (q < MAXIDX) sm.s.idxB[q] = 4*i+3; }
                }
            }
        }
    }
    __syncthreads();

    // wait for transpose completion
    if (tid == 0) {
        while (atomicAdd(&g_done, 0) < NT) __nanosleep(128);
    }
    __syncthreads();
    __threadfence();

    // ---------------- gather ----------------
    const float4 bias = *reinterpret_cast<const float4*>(ft_b + 4 * tid);
    float4 accW = bias, accB = bias;
    const int nW = min(sm.s.cw, MAXIDX);
#pragma unroll 4
    for (int j = 0; j < nW; j++) {
        const uint2 raw = *reinterpret_cast<const uint2*>(
            g_ftT + (size_t)sm.s.idxW[j] * HID + 4 * tid);
        const float2 lo = __half22float2(*reinterpret_cast<const __half2*>(&raw.x));
        const float2 hi = __half22float2(*reinterpret_cast<const __half2*>(&raw.y));
        accW.x += lo.x; accW.y += lo.y; accW.z += hi.x; accW.w += hi.y;
    }
    const int nB = min(sm.s.cb, MAXIDX);
#pragma unroll 4
    for (int j = 0; j < nB; j++) {
        const uint2 raw = *reinterpret_cast<const uint2*>(
            g_ftT + (size_t)sm.s.idxB[j] * HID + 4 * tid);
        const float2 lo = __half22float2(*reinterpret_cast<const __half2*>(&raw.x));
        const float2 hi = __half22float2(*reinterpret_cast<const __half2*>(&raw.y));
        accB.x += lo.x; accB.y += lo.y; accB.z += hi.x; accB.w += hi.y;
    }

    // stm select + clip + store h1 (fp16)
    const float s = __ldg(stm + b);
    float cw[4] = {fminf(fmaxf(accW.x,0.f),1.f), fminf(fmaxf(accW.y,0.f),1.f),
                   fminf(fmaxf(accW.z,0.f),1.f), fminf(fmaxf(accW.w,0.f),1.f)};
    float cb[4] = {fminf(fmaxf(accB.x,0.f),1.f), fminf(fmaxf(accB.y,0.f),1.f),
                   fminf(fmaxf(accB.z,0.f),1.f), fminf(fmaxf(accB.w,0.f),1.f)};
    __half* o = g_h1 + (size_t)b * HID2;
    uint2 pf, ps;
    *reinterpret_cast<__half2*>(&pf.x) = __floats2half2_rn(
        s*cw[0]+(1.f-s)*cb[0], s*cw[1]+(1.f-s)*cb[1]);
    *reinterpret_cast<__half2*>(&pf.y) = __floats2half2_rn(
        s*cw[2]+(1.f-s)*cb[2], s*cw[3]+(1.f-s)*cb[3]);
    *reinterpret_cast<__half2*>(&ps.x) = __floats2half2_rn(
        s*cb[0]+(1.f-s)*cw[0], s*cb[1]+(1.f-s)*cw[1]);
    *reinterpret_cast<__half2*>(&ps.y) = __floats2half2_rn(
        s*cb[2]+(1.f-s)*cw[2], s*cb[3]+(1.f-s)*cw[3]);
    *reinterpret_cast<uint2*>(o + 4 * tid)       = pf;
    *reinterpret_cast<uint2*>(o + HID + 4 * tid) = ps;
}

// =========================================================================
// Kernel 2: MLP head (round-4 proven version, verbatim).
// TB=32 rows/CTA, 256 threads, 4 rows x 2 outs per thread.
// =========================================================================
#define T2    256
#define TB    32
#define CHUNK 64
#define NCH   (HID2 / CHUNK)
#define HPAD  36
#define WPAD  66

__global__ __launch_bounds__(T2) void mlp_kernel(
    const float* __restrict__ l1_w, const float* __restrict__ l1_b,
    const float* __restrict__ l2_w, const float* __restrict__ l2_b,
    const float* __restrict__ l3_w, const float* __restrict__ l3_b,
    float* __restrict__ out, int out_size)
{
    __shared__ __align__(16) float hst[2][CHUNK][HPAD];
    __shared__ __align__(16) float wst[2][CHUNK][WPAD];
    __shared__ float l2s[NL2][NL1 + 1];
    __shared__ float h2s[TB][NL1 + 1];
    __shared__ float h3s[TB][NL2 + 1];

    const int tid  = threadIdx.x;
    const int row0 = blockIdx.x * TB;
    const int tx   = tid & 31;
    const int ty   = tid >> 5;

    for (int i = tid; i < NL2 * NL1; i += T2) l2s[i >> 6][i & 63] = l2_w[i];

    __half2 hreg[4];
    float   wreg[16];
    {
#pragma unroll
        for (int u = 0; u < 4; u++) {
            int idx = tid + u * T2; int r = idx >> 5, kp = idx & 31;
            hreg[u] = *reinterpret_cast<const __half2*>(
                g_h1 + (size_t)(row0 + r) * HID2 + 2 * kp);
        }
#pragma unroll
        for (int u = 0; u < 16; u++) {
            int idx = tid + u * T2; int oo = idx >> 6, kk = idx & 63;
            wreg[u] = __ldg(l1_w + (size_t)oo * HID2 + kk);
        }
#pragma unroll
        for (int u = 0; u < 4; u++) {
            int idx = tid + u * T2; int r = idx >> 5, kp = idx & 31;
            float2 f = __half22float2(hreg[u]);
            hst[0][2 * kp][r]     = f.x;
            hst[0][2 * kp + 1][r] = f.y;
        }
#pragma unroll
        for (int u = 0; u < 16; u++) {
            int idx = tid + u * T2; int oo = idx >> 6, kk = idx & 63;
            wst[0][kk][oo] = wreg[u];
        }
    }
    __syncthreads();

    float acc[4][2];
#pragma unroll
    for (int i = 0; i < 4; i++) { acc[i][0] = 0.f; acc[i][1] = 0.f; }

    for (int c = 0; c < NCH; c++) {
        const int buf = c & 1;
        if (c + 1 < NCH) {
            const int kc = (c + 1) * CHUNK;
#pragma unroll
            for (int u = 0; u < 4; u++) {
                int idx = tid + u * T2; int r = idx >> 5, kp = idx & 31;
                hreg[u] = *reinterpret_cast<const __half2*>(
                    g_h1 + (size_t)(row0 + r) * HID2 + kc + 2 * kp);
            }
#pragma unroll
            for (int u = 0; u < 16; u++) {
                int idx = tid + u * T2; int oo = idx >> 6, kk = idx & 63;
                wreg[u] = __ldg(l1_w + (size_t)oo * HID2 + kc + kk);
            }
        }
#pragma unroll 16
        for (int k = 0; k < CHUNK; k++) {
            const float4 h = *reinterpret_cast<const float4*>(&hst[buf][k][4 * ty]);
            const float2 w = *reinterpret_cast<const float2*>(&wst[buf][k][2 * tx]);
            acc[0][0] = fmaf(h.x, w.x, acc[0][0]); acc[0][1] = fmaf(h.x, w.y, acc[0][1]);
            acc[1][0] = fmaf(h.y, w.x, acc[1][0]); acc[1][1] = fmaf(h.y, w.y, acc[1][1]);
            acc[2][0] = fmaf(h.z, w.x, acc[2][0]); acc[2][1] = fmaf(h.z, w.y, acc[2][1]);
            acc[3][0] = fmaf(h.w, w.x, acc[3][0]); acc[3][1] = fmaf(h.w, w.y, acc[3][1]);
        }
        if (c + 1 < NCH) {
            const int nb = (c + 1) & 1;
#pragma unroll
            for (int u = 0; u < 4; u++) {
                int idx = tid + u * T2; int r = idx >> 5, kp = idx & 31;
                float2 f = __half22float2(hreg[u]);
                hst[nb][2 * kp][r]     = f.x;
                hst[nb][2 * kp + 1][r] = f.y;
            }
#pragma unroll
            for (int u = 0; u < 16; u++) {
                int idx = tid + u * T2; int oo = idx >> 6, kk = idx & 63;
                wst[nb][kk][oo] = wreg[u];
            }
        }
        __syncthreads();
    }

#pragma unroll
    for (int i = 0; i < 4; i++) {
#pragma unroll
        for (int j = 0; j < 2; j++) {
            float v = acc[i][j] + __ldg(l1_b + 2 * tx + j);
            h2s[4 * ty + i][2 * tx + j] = fminf(fmaxf(v, 0.f), 1.f);
        }
    }
    __syncthreads();

    for (int p = tid; p < TB * NL2; p += T2) {
        int r = p >> 5, oo = p & 31;
        float s = __ldg(l2_b + oo);
#pragma unroll
        for (int k = 0; k < NL1; k++) s = fmaf(h2s[r][k], l2s[oo][k], s);
        h3s[r][oo] = fminf(fmaxf(s, 0.f), 1.f);
    }
    __syncthreads();

    if (tid < TB) {
        float s = __ldg(l3_b);
#pragma unroll
        for (int k = 0; k < NL2; k++) s = fmaf(h3s[tid][k], __ldg(l3_w + k), s);
        float sig = 1.f / (1.f + expf(-s));
        int r = row0 + tid;
        if (out_size >= 2 * BATCH) {
            out[r]         = sig;
            out[BATCH + r] = s;
        } else {
            out[r] = sig;
        }
    }
}

// =========================================================================
extern "C" void kernel_launch(void* const* d_in, const int* in_sizes, int n_in,
                              void* d_out, int out_size)
{
    const float* wf    = (const float*)d_in[0];
    const float* bfeat = (const float*)d_in[1];
    const float* stm   = (const float*)d_in[2];
    const float* ft_w  = (const float*)d_in[3];
    const float* ft_b  = (const float*)d_in[4];
    const float* l1_w  = (const float*)d_in[5];
    const float* l1_b  = (const float*)d_in[6];
    const float* l2_w  = (const float*)d_in[7];
    const float* l2_b  = (const float*)d_in[8];
    const float* l3_w  = (const float*)d_in[9];
    const float* l3_b  = (const float*)d_in[10];
    float* out = (float*)d_out;

    reset_kernel<<<1, 1>>>();
    mega_kernel<<<NT + BATCH, T1>>>(wf, bfeat, stm, ft_w, ft_b);
    mlp_kernel<<<BATCH / TB, T2>>>(l1_w, l1_b, l2_w, l2_b, l3_w, l3_b, out, out_size);
}

// round 11
// speedup vs baseline: 1.5200x; 1.0165x over previous
#include <cuda_runtime.h>
#include <cuda_fp16.h>
#include <math.h>

#define BATCH 4096
#define FEAT  40960
#define HID   1024
#define HID2  2048
#define NL1   64
#define NL2   32
#define GRP   32
#define NGRP  (BATCH / GRP)     // 128
#define NQ    4                 // k-quarters
#define QK    (HID2 / NQ)       // 512

// ---------------- static device scratch (no allocs allowed) ----------------
__device__ __half g_ftT[(size_t)FEAT * HID];            // 83.9 MB
__device__ __half g_h1[(size_t)BATCH * HID2];           // 16.8 MB
__device__ float  g_part[(size_t)NQ * NGRP * GRP * NL1]; // 4.2 MB l1 partials
__device__ int    g_done;

// =========================================================================
// Reset kernel
// =========================================================================
__global__ void reset_kernel() { g_done = 0; }

// =========================================================================
// Mega-kernel (round-4 exact):
//   CTAs [0, NT)        : transpose ft_w -> g_ftT (fp16), signal.
//   CTAs [NT, NT+BATCH) : scan -> wait -> gather -> h1 (fp16).
// =========================================================================
#define T1      256
#define NT      512
#define MAXIDX  256
#define NTILE_F (FEAT / 32)                 // 1280
#define NTILES  (NTILE_F * (HID / 64))      // 20480

__global__ __launch_bounds__(T1) void mega_kernel(
    const float* __restrict__ wf,    // [B, FEAT]
    const float* __restrict__ bfeat, // [B, FEAT]
    const float* __restrict__ stm,   // [B, 1]
    const float* __restrict__ ftw,   // [HID, FEAT]
    const float* __restrict__ ft_b)  // [HID]
{
    __shared__ union {
        float tile[64][33];
        struct { int idxW[MAXIDX]; int idxB[MAXIDX]; int cw; int cb; } s;
    } sm;

    const int tid = threadIdx.x;

    if (blockIdx.x < NT) {
        // ---------------- transpose: 40 tiles of 64h x 32f per CTA ----------------
        for (int t = blockIdx.x; t < NTILES; t += NT) {
            const int f0 = (t % NTILE_F) * 32;
            const int h0 = (t / NTILE_F) * 64;
#pragma unroll
            for (int u = 0; u < 8; u++) {
                int idx = tid + u * T1;
                int hl = idx >> 5, fl = idx & 31;
                sm.tile[hl][fl] = __ldcs(ftw + (size_t)(h0 + hl) * FEAT + f0 + fl);
            }
            __syncthreads();
#pragma unroll
            for (int u = 0; u < 4; u++) {
                int idx = tid + u * T1;
                int fl = idx >> 5, hp = idx & 31;
                __half2 v = __floats2half2_rn(sm.tile[2 * hp][fl], sm.tile[2 * hp + 1][fl]);
                *reinterpret_cast<__half2*>(g_ftT + (size_t)(f0 + fl) * HID + h0 + 2 * hp) = v;
            }
            __syncthreads();
        }
        __threadfence();
        __syncthreads();
        if (tid == 0) atomicAdd(&g_done, 1);
        return;
    }

    // ---------------- scan ----------------
    const int b = blockIdx.x - NT;

    if (tid == 0) { sm.s.cw = 0; sm.s.cb = 0; }
    __syncthreads();
    {
        const float4* pw = (const float4*)(wf    + (size_t)b * FEAT);
        const float4* pb = (const float4*)(bfeat + (size_t)b * FEAT);
        for (int base = 0; base < FEAT / 4; base += 4 * T1) {
            float4 v[4], w[4];
#pragma unroll
            for (int u = 0; u < 4; u++) {
                v[u] = __ldcs(pw + base + tid + u * T1);
                w[u] = __ldcs(pb + base + tid + u * T1);
            }
#pragma unroll
            for (int u = 0; u < 4; u++) {
                int i = base + tid + u * T1;
                if (v[u].x != 0.f) { int q = atomicAdd(&sm.s.cw, 1); if (q < MAXIDX) sm.s.idxW[q] = 4*i;   }
                if (v[u].y != 0.f) { int q = atomicAdd(&sm.s.cw, 1); if (q < MAXIDX) sm.s.idxW[q] = 4*i+1; }
                if (v[u].z != 0.f) { int q = atomicAdd(&sm.s.cw, 1); if (q < MAXIDX) sm.s.idxW[q] = 4*i+2; }
                if (v[u].w != 0.f) { int q = atomicAdd(&sm.s.cw, 1); if (q < MAXIDX) sm.s.idxW[q] = 4*i+3; }
                if (w[u].x != 0.f) { int q = atomicAdd(&sm.s.cb, 1); if (q < MAXIDX) sm.s.idxB[q] = 4*i;   }
                if (w[u].y != 0.f) { int q = atomicAdd(&sm.s.cb, 1); if (q < MAXIDX) sm.s.idxB[q] = 4*i+1; }
                if (w[u].z != 0.f) { int q = atomicAdd(&sm.s.cb, 1); if (q < MAXIDX) sm.s.idxB[q] = 4*i+2; }
                if (w[u].w != 0.f) { int q = atomicAdd(&sm.s.cb, 1); if (q < MAXIDX) sm.s.idxB[q] = 4*i+3; }
            }
        }
    }
    __syncthreads();

    // wait for transpose completion
    if (tid == 0) {
        while (atomicAdd(&g_done, 0) < NT) __nanosleep(128);
    }
    __syncthreads();
    __threadfence();

    // ---------------- gather ----------------
    const float4 bias = *reinterpret_cast<const float4*>(ft_b + 4 * tid);
    float4 accW = bias, accB = bias;
    const int nW = min(sm.s.cw, MAXIDX);
#pragma unroll 4
    for (int j = 0; j < nW; j++) {
        const uint2 raw = *reinterpret_cast<const uint2*>(
            g_ftT + (size_t)sm.s.idxW[j] * HID + 4 * tid);
        const float2 lo = __half22float2(*reinterpret_cast<const __half2*>(&raw.x));
        const float2 hi = __half22float2(*reinterpret_cast<const __half2*>(&raw.y));
        accW.x += lo.x; accW.y += lo.y; accW.z += hi.x; accW.w += hi.y;
    }
    const int nB = min(sm.s.cb, MAXIDX);
#pragma unroll 4
    for (int j = 0; j < nB; j++) {
        const uint2 raw = *reinterpret_cast<const uint2*>(
            g_ftT + (size_t)sm.s.idxB[j] * HID + 4 * tid);
        const float2 lo = __half22float2(*reinterpret_cast<const __half2*>(&raw.x));
        const float2 hi = __half22float2(*reinterpret_cast<const __half2*>(&raw.y));
        accB.x += lo.x; accB.y += lo.y; accB.z += hi.x; accB.w += hi.y;
    }

    // stm select + clip + store h1 (fp16)
    const float s = __ldg(stm + b);
    float cw[4] = {fminf(fmaxf(accW.x,0.f),1.f), fminf(fmaxf(accW.y,0.f),1.f),
                   fminf(fmaxf(accW.z,0.f),1.f), fminf(fmaxf(accW.w,0.f),1.f)};
    float cb[4] = {fminf(fmaxf(accB.x,0.f),1.f), fminf(fmaxf(accB.y,0.f),1.f),
                   fminf(fmaxf(accB.z,0.f),1.f), fminf(fmaxf(accB.w,0.f),1.f)};
    __half* o = g_h1 + (size_t)b * HID2;
    uint2 pf, ps;
    *reinterpret_cast<__half2*>(&pf.x) = __floats2half2_rn(
        s*cw[0]+(1.f-s)*cb[0], s*cw[1]+(1.f-s)*cb[1]);
    *reinterpret_cast<__half2*>(&pf.y) = __floats2half2_rn(
        s*cw[2]+(1.f-s)*cb[2], s*cw[3]+(1.f-s)*cb[3]);
    *reinterpret_cast<__half2*>(&ps.x) = __floats2half2_rn(
        s*cb[0]+(1.f-s)*cw[0], s*cb[1]+(1.f-s)*cw[1]);
    *reinterpret_cast<__half2*>(&ps.y) = __floats2half2_rn(
        s*cb[2]+(1.f-s)*cw[2], s*cb[3]+(1.f-s)*cw[3]);
    *reinterpret_cast<uint2*>(o + 4 * tid)       = pf;
    *reinterpret_cast<uint2*>(o + HID + 4 * tid) = ps;
}

// =========================================================================
// mlp1: l1 partial GEMM. grid = NGRP*NQ = 512 CTAs, 256 threads.
// CTA (grp, q): rows [32*grp, +32), k in [512*q, +512). 4x2 thread tile.
// Writes 32x64 fp32 partials to g_part[q][grp].
// =========================================================================
#define T2    256
#define TB    32
#define CHUNK 64
#define NCHQ  (QK / CHUNK)   // 8
#define HPAD  36
#define WPAD  66

__global__ __launch_bounds__(T2) void mlp1_kernel(const float* __restrict__ l1_w)
{
    __shared__ __align__(16) float hst[2][CHUNK][HPAD];   // 18.4 KB
    __shared__ __align__(16) float wst[2][CHUNK][WPAD];   // 33.8 KB

    const int tid  = threadIdx.x;
    const int grp  = blockIdx.x >> 2;
    const int q    = blockIdx.x & 3;
    const int row0 = grp * TB;
    const int kb   = q * QK;
    const int tx   = tid & 31;   // out pair {2tx, 2tx+1}
    const int ty   = tid >> 5;   // row quad {4ty..4ty+3}

    __half2 hreg[4];
    float   wreg[16];
    {
#pragma unroll
        for (int u = 0; u < 4; u++) {
            int idx = tid + u * T2; int r = idx >> 5, kp = idx & 31;
            hreg[u] = *reinterpret_cast<const __half2*>(
                g_h1 + (size_t)(row0 + r) * HID2 + kb + 2 * kp);
        }
#pragma unroll
        for (int u = 0; u < 16; u++) {
            int idx = tid + u * T2; int oo = idx >> 6, kk = idx & 63;
            wreg[u] = __ldg(l1_w + (size_t)oo * HID2 + kb + kk);
        }
#pragma unroll
        for (int u = 0; u < 4; u++) {
            int idx = tid + u * T2; int r = idx >> 5, kp = idx & 31;
            float2 f = __half22float2(hreg[u]);
            hst[0][2 * kp][r]     = f.x;
            hst[0][2 * kp + 1][r] = f.y;
        }
#pragma unroll
        for (int u = 0; u < 16; u++) {
            int idx = tid + u * T2; int oo = idx >> 6, kk = idx & 63;
            wst[0][kk][oo] = wreg[u];
        }
    }
    __syncthreads();

    float acc[4][2];
#pragma unroll
    for (int i = 0; i < 4; i++) { acc[i][0] = 0.f; acc[i][1] = 0.f; }

    for (int c = 0; c < NCHQ; c++) {
        const int buf = c & 1;
        if (c + 1 < NCHQ) {
            const int kc = kb + (c + 1) * CHUNK;
#pragma unroll
            for (int u = 0; u < 4; u++) {
                int idx = tid + u * T2; int r = idx >> 5, kp = idx & 31;
                hreg[u] = *reinterpret_cast<const __half2*>(
                    g_h1 + (size_t)(row0 + r) * HID2 + kc + 2 * kp);
            }
#pragma unroll
            for (int u = 0; u < 16; u++) {
                int idx = tid + u * T2; int oo = idx >> 6, kk = idx & 63;
                wreg[u] = __ldg(l1_w + (size_t)oo * HID2 + kc + kk);
            }
        }
#pragma unroll 16
        for (int k = 0; k < CHUNK; k++) {
            const float4 h = *reinterpret_cast<const float4*>(&hst[buf][k][4 * ty]);
            const float2 w = *reinterpret_cast<const float2*>(&wst[buf][k][2 * tx]);
            acc[0][0] = fmaf(h.x, w.x, acc[0][0]); acc[0][1] = fmaf(h.x, w.y, acc[0][1]);
            acc[1][0] = fmaf(h.y, w.x, acc[1][0]); acc[1][1] = fmaf(h.y, w.y, acc[1][1]);
            acc[2][0] = fmaf(h.z, w.x, acc[2][0]); acc[2][1] = fmaf(h.z, w.y, acc[2][1]);
            acc[3][0] = fmaf(h.w, w.x, acc[3][0]); acc[3][1] = fmaf(h.w, w.y, acc[3][1]);
        }
        if (c + 1 < NCHQ) {
            const int nb = (c + 1) & 1;
#pragma unroll
            for (int u = 0; u < 4; u++) {
                int idx = tid + u * T2; int r = idx >> 5, kp = idx & 31;
                float2 f = __half22float2(hreg[u]);
                hst[nb][2 * kp][r]     = f.x;
                hst[nb][2 * kp + 1][r] = f.y;
            }
#pragma unroll
            for (int u = 0; u < 16; u++) {
                int idx = tid + u * T2; int oo = idx >> 6, kk = idx & 63;
                wst[nb][kk][oo] = wreg[u];
            }
        }
        __syncthreads();
    }

    // store partials: g_part[q][grp][row][out]
    float* dst = g_part + (((size_t)q * NGRP + grp) * TB) * NL1;
#pragma unroll
    for (int i = 0; i < 4; i++) {
        float2 v = make_float2(acc[i][0], acc[i][1]);
        *reinterpret_cast<float2*>(dst + (4 * ty + i) * NL1 + 2 * tx) = v;
    }
}

// =========================================================================
// mlp2: reduce partials + bias + clip -> l2 -> l3 -> sigmoid. 128 CTAs.
// =========================================================================
__global__ __launch_bounds__(T2) void mlp2_kernel(
    const float* __restrict__ l1_b,
    const float* __restrict__ l2_w, const float* __restrict__ l2_b,
    const float* __restrict__ l3_w, const float* __restrict__ l3_b,
    float* __restrict__ out, int out_size)
{
    __shared__ float h2s[GRP][NL1 + 1];
    __shared__ float h3s[GRP][NL2 + 1];
    __shared__ float l2s[NL2][NL1 + 1];

    const int tid = threadIdx.x;
    const int grp = blockIdx.x;
    const int row0 = grp * GRP;

    for (int i = tid; i < NL2 * NL1; i += T2) l2s[i >> 6][i & 63] = l2_w[i];

    // sum 4 quarters + bias, clip -> h2s  (2048 entries, 8/thread)
    const float* base = g_part + (size_t)grp * TB * NL1;
    for (int p = tid; p < GRP * NL1; p += T2) {
        int r = p >> 6, o = p & 63;
        float s = __ldg(l1_b + o);
#pragma unroll
        for (int q = 0; q < NQ; q++)
            s += base[(size_t)q * NGRP * TB * NL1 + r * NL1 + o];
        h2s[r][o] = fminf(fmaxf(s, 0.f), 1.f);
    }
    __syncthreads();

    // l2: 32 rows x 32 outs = 1024 -> 4/thread
    for (int p = tid; p < GRP * NL2; p += T2) {
        int r = p >> 5, oo = p & 31;
        float s = __ldg(l2_b + oo);
#pragma unroll
        for (int k = 0; k < NL1; k++) s = fmaf(h2s[r][k], l2s[oo][k], s);
        h3s[r][oo] = fminf(fmaxf(s, 0.f), 1.f);
    }
    __syncthreads();

    // l3 + sigmoid
    if (tid < GRP) {
        float s = __ldg(l3_b);
#pragma unroll
        for (int k = 0; k < NL2; k++) s = fmaf(h3s[tid][k], __ldg(l3_w + k), s);
        float sig = 1.f / (1.f + expf(-s));
        int r = row0 + tid;
        if (out_size >= 2 * BATCH) {
            out[r]         = sig;
            out[BATCH + r] = s;
        } else {
            out[r] = sig;
        }
    }
}

// =========================================================================
extern "C" void kernel_launch(void* const* d_in, const int* in_sizes, int n_in,
                              void* d_out, int out_size)
{
    const float* wf    = (const float*)d_in[0];
    const float* bfeat = (const float*)d_in[1];
    const float* stm   = (const float*)d_in[2];
    const float* ft_w  = (const float*)d_in[3];
    const float* ft_b  = (const float*)d_in[4];
    const float* l1_w  = (const float*)d_in[5];
    const float* l1_b  = (const float*)d_in[6];
    const float* l2_w  = (const float*)d_in[7];
    const float* l2_b  = (const float*)d_in[8];
    const float* l3_w  = (const float*)d_in[9];
    const float* l3_b  = (const float*)d_in[10];
    float* out = (float*)d_out;

    reset_kernel<<<1, 1>>>();
    mega_kernel<<<NT + BATCH, T1>>>(wf, bfeat, stm, ft_w, ft_b);
    mlp1_kernel<<<NGRP * NQ, T2>>>(l1_w);
    mlp2_kernel<<<NGRP, T2>>>(l1_b, l2_w, l2_b, l3_w, l3_b, out, out_size);
}